// round 1
// baseline (speedup 1.0000x reference)
#include <cuda_runtime.h>

#define BB   64      // batch
#define TT   256     // time
#define DD   512     // input dim
#define HH   512     // hidden dim
#define NCOL 1024    // output cols per step = H (h_new) + D (o)
#define NCTA 128     // scan grid
#define CPC  8       // columns per CTA in scan

// ---------------- scratch (static device allocations only) ----------------
__device__ float g_P[(size_t)TT * BB * NCOL];    // x-part preactivations (reused per layer)
__device__ float g_out0[(size_t)TT * BB * DD];   // layer0 output, row m = t*B+b
__device__ float g_hT[2][HH][BB];                // transposed hidden, double buffered
__device__ float g_W0x[DD * NCOL];
__device__ float g_W0r[HH * NCOL];
__device__ float g_W1x[DD * NCOL];
__device__ float g_W1r[HH * NCOL];
__device__ float g_b0[NCOL];
__device__ float g_b1[NCOL];
__device__ unsigned int g_bar;

// Accurate tanh independent of --use_fast_math (expm1f is not fast-mathed).
__device__ __forceinline__ float tanh_acc(float x) {
    float ax = fabsf(x);
    float u  = expm1f(-2.0f * ax);      // in [-1, 0]
    float r  = -u / (2.0f + u);
    return x >= 0.0f ? r : -r;
}

// ---------------- weight packing: W = [Wh | Wo], split x-rows / h-rows ----
__global__ void pack_weights(const float* __restrict__ Wh0, const float* __restrict__ Wo0,
                             const float* __restrict__ bh0, const float* __restrict__ bo0,
                             const float* __restrict__ Wh1, const float* __restrict__ Wo1,
                             const float* __restrict__ bh1, const float* __restrict__ bo1)
{
    int idx = blockIdx.x * blockDim.x + threadIdx.x;
    if (idx >= DD * NCOL) return;
    int k = idx >> 10;
    int n = idx & (NCOL - 1);
    bool hcol = (n < HH);
    int c = hcol ? n : n - HH;
    g_W0x[idx] = hcol ? Wh0[k * HH + c]        : Wo0[k * DD + c];
    g_W0r[idx] = hcol ? Wh0[(DD + k) * HH + c] : Wo0[(DD + k) * DD + c];
    g_W1x[idx] = hcol ? Wh1[k * HH + c]        : Wo1[k * DD + c];
    g_W1r[idx] = hcol ? Wh1[(DD + k) * HH + c] : Wo1[(DD + k) * DD + c];
    if (idx < NCOL) {
        g_b0[idx] = hcol ? bh0[c] : bo0[c];
        g_b1[idx] = hcol ? bh1[c] : bo1[c];
    }
}

// ---------------- per-layer init (also resets the grid barrier) ----------
__global__ void init_layer0(const float* __restrict__ enc) {
    int idx = blockIdx.x * blockDim.x + threadIdx.x;
    if (idx < HH * BB) {
        int k = idx >> 6, b = idx & 63;
        g_hT[0][k][b] = enc[b * HH + k];   // transpose encoder_output [B,H] -> [H,B]
    }
    if (idx == 0) g_bar = 0u;
}

__global__ void init_layer1() {
    int idx = blockIdx.x * blockDim.x + threadIdx.x;
    if (idx < HH * BB) g_hT[0][idx >> 6][idx & 63] = 0.0f;
    if (idx == 0) g_bar = 0u;
}

// ---------------- big parallel GEMM: P[m, 0:1024] = A_row(m) @ Wx --------
// m = t*B + b ; row offset = (m%64)*sB + (m/64)*sT ; K = 512, N = 1024.
__global__ __launch_bounds__(256)
void gemm_kernel(const float* __restrict__ Ain, int layer, int sB, int sT)
{
    const float* __restrict__ A  = Ain ? Ain : g_out0;
    const float* __restrict__ Bm = layer ? g_W1x : g_W0x;
    float* __restrict__ C = g_P;

    __shared__ __align__(16) float As[16][128];
    __shared__ __align__(16) float Bs[16][128];

    const int tid = threadIdx.x;
    const int m0 = blockIdx.y * 128;
    const int n0 = blockIdx.x * 128;

    const int ai = tid >> 2;            // 0..63
    const int ak = (tid & 3) << 2;      // 0,4,8,12
    const int mg0 = m0 + ai;
    const int mg1 = m0 + ai + 64;
    const float* ap0 = A + (size_t)(mg0 & 63) * sB + (size_t)(mg0 >> 6) * sT + ak;
    const float* ap1 = A + (size_t)(mg1 & 63) * sB + (size_t)(mg1 >> 6) * sT + ak;

    const int bk = tid >> 5;            // 0..7
    const int bn = (tid & 31) << 2;     // 0..124
    const float* bp = Bm + (size_t)bk * NCOL + n0 + bn;

    const int ty = tid >> 4, tx = tid & 15;

    float acc[8][8];
#pragma unroll
    for (int i = 0; i < 8; ++i)
#pragma unroll
        for (int j = 0; j < 8; ++j) acc[i][j] = 0.0f;

    for (int k0 = 0; k0 < DD; k0 += 16) {
        float4 av0 = *(const float4*)(ap0 + k0);
        float4 av1 = *(const float4*)(ap1 + k0);
        float4 bv0 = *(const float4*)(bp + (size_t)k0 * NCOL);
        float4 bv1 = *(const float4*)(bp + (size_t)(k0 + 8) * NCOL);
        __syncthreads();
        As[ak + 0][ai] = av0.x; As[ak + 1][ai] = av0.y;
        As[ak + 2][ai] = av0.z; As[ak + 3][ai] = av0.w;
        As[ak + 0][ai + 64] = av1.x; As[ak + 1][ai + 64] = av1.y;
        As[ak + 2][ai + 64] = av1.z; As[ak + 3][ai + 64] = av1.w;
        *(float4*)&Bs[bk][bn]     = bv0;
        *(float4*)&Bs[bk + 8][bn] = bv1;
        __syncthreads();
#pragma unroll
        for (int k = 0; k < 16; ++k) {
            float4 x0 = *(const float4*)&As[k][ty * 8];
            float4 x1 = *(const float4*)&As[k][ty * 8 + 4];
            float4 y0 = *(const float4*)&Bs[k][tx * 8];
            float4 y1 = *(const float4*)&Bs[k][tx * 8 + 4];
            float xa[8] = {x0.x, x0.y, x0.z, x0.w, x1.x, x1.y, x1.z, x1.w};
            float yb[8] = {y0.x, y0.y, y0.z, y0.w, y1.x, y1.y, y1.z, y1.w};
#pragma unroll
            for (int i = 0; i < 8; ++i)
#pragma unroll
                for (int j = 0; j < 8; ++j)
                    acc[i][j] += xa[i] * yb[j];
        }
    }
#pragma unroll
    for (int i = 0; i < 8; ++i) {
        float* cp = C + (size_t)(m0 + ty * 8 + i) * NCOL + n0 + tx * 8;
        *(float4*)cp       = make_float4(acc[i][0], acc[i][1], acc[i][2], acc[i][3]);
        *(float4*)(cp + 4) = make_float4(acc[i][4], acc[i][5], acc[i][6], acc[i][7]);
    }
}

// ---------------- persistent sequential scan ------------------------------
// 128 CTAs, each owns 8 columns of [h_new | o]. One global spin barrier per step.
__global__ __launch_bounds__(256)
void scan_kernel(int layer, float* __restrict__ dout)
{
    const float* __restrict__ Wr  = layer ? g_W1r : g_W0r;
    const float* __restrict__ bia = layer ? g_b1  : g_b0;

    __shared__ __align__(16) float Ws[HH * CPC];       // W_r slice [k][j]
    __shared__ __align__(16) float red[8 * CPC * BB];  // warp partials [w][j][r]
    __shared__ float bs[CPC];

    const int tid = threadIdx.x;
    const int n0  = blockIdx.x * CPC;

    for (int idx = tid; idx < HH * CPC; idx += 256) {
        int k = idx >> 3, j = idx & 7;
        Ws[idx] = Wr[k * NCOL + n0 + j];
    }
    if (tid < CPC) bs[tid] = bia[n0 + tid];
    __syncthreads();

    const int w  = tid >> 5;            // warp id: owns k in [w*64, w*64+64)
    const int ln = tid & 31;            // lane: owns rows 2*ln, 2*ln+1
    const int rr = tid >> 2;            // reduce: row
    const int jp = (tid & 3) << 1;      // reduce: col pair
    const bool isH = (n0 < HH);
    const float b0v = bs[jp], b1v = bs[jp + 1];

    for (int t = 0; t < TT; ++t) {
        const float2* __restrict__ hp = (const float2*)&g_hT[t & 1][0][0];
        float a0[8] = {0, 0, 0, 0, 0, 0, 0, 0};
        float a1[8] = {0, 0, 0, 0, 0, 0, 0, 0};
        const int kb = w * 64;
#pragma unroll 8
        for (int kk = 0; kk < 64; ++kk) {
            const int k = kb + kk;
            const float2 hv = hp[k * 32 + ln];
            const float4 wa = *(const float4*)(Ws + k * 8);
            const float4 wb = *(const float4*)(Ws + k * 8 + 4);
            a0[0] += hv.x * wa.x; a0[1] += hv.x * wa.y;
            a0[2] += hv.x * wa.z; a0[3] += hv.x * wa.w;
            a0[4] += hv.x * wb.x; a0[5] += hv.x * wb.y;
            a0[6] += hv.x * wb.z; a0[7] += hv.x * wb.w;
            a1[0] += hv.y * wa.x; a1[1] += hv.y * wa.y;
            a1[2] += hv.y * wa.z; a1[3] += hv.y * wa.w;
            a1[4] += hv.y * wb.x; a1[5] += hv.y * wb.y;
            a1[6] += hv.y * wb.z; a1[7] += hv.y * wb.w;
        }
        const int r0 = ln * 2;
#pragma unroll
        for (int j = 0; j < 8; ++j)
            *(float2*)&red[(w * 8 + j) * BB + r0] = make_float2(a0[j], a1[j]);
        __syncthreads();

        float s0 = 0.0f, s1 = 0.0f;
#pragma unroll
        for (int ww = 0; ww < 8; ++ww) {
            s0 += red[(ww * 8 + jp)     * BB + rr];
            s1 += red[(ww * 8 + jp + 1) * BB + rr];
        }
        const float2 pv = *(const float2*)&g_P[((size_t)t * BB + rr) * NCOL + n0 + jp];
        s0 = tanh_acc(s0 + pv.x + b0v);
        s1 = tanh_acc(s1 + pv.y + b1v);

        if (isH) {
            float* hN = &g_hT[(t + 1) & 1][0][0];
            hN[(n0 + jp)     * BB + rr] = s0;
            hN[(n0 + jp + 1) * BB + rr] = s1;
        } else {
            const int c = n0 - HH + jp;
            if (layer == 0)
                *(float2*)&g_out0[((size_t)t * BB + rr) * DD + c] = make_float2(s0, s1);
            else
                *(float2*)&dout[((size_t)rr * TT + t) * DD + c]   = make_float2(s0, s1);
        }

        __syncthreads();
        if (tid == 0) {
            __threadfence();
            atomicAdd(&g_bar, 1u);
            const unsigned int target = (unsigned int)(t + 1) * NCTA;
            while (*((volatile unsigned int*)&g_bar) < target) { }
            __threadfence();
        }
        __syncthreads();
    }
}

// ---------------- launch ---------------------------------------------------
extern "C" void kernel_launch(void* const* d_in, const int* in_sizes, int n_in,
                              void* d_out, int out_size)
{
    const float* x   = (const float*)d_in[0];
    const float* enc = (const float*)d_in[1];
    const float* Wh0 = (const float*)d_in[2];
    const float* bh0 = (const float*)d_in[3];
    const float* Wo0 = (const float*)d_in[4];
    const float* bo0 = (const float*)d_in[5];
    const float* Wh1 = (const float*)d_in[6];
    const float* bh1 = (const float*)d_in[7];
    const float* Wo1 = (const float*)d_in[8];
    const float* bo1 = (const float*)d_in[9];
    float* out = (float*)d_out;

    pack_weights<<<(DD * NCOL + 255) / 256, 256>>>(Wh0, Wo0, bh0, bo0, Wh1, Wo1, bh1, bo1);

    // Layer 0: P = x @ W0x ; scan with h0 = encoder_output
    init_layer0<<<(HH * BB + 255) / 256, 256>>>(enc);
    gemm_kernel<<<dim3(8, 128), 256>>>(x, 0, TT * DD, DD);       // x is [B][T][D]
    scan_kernel<<<NCTA, 256>>>(0, nullptr);

    // Layer 1: P = out0 @ W1x ; scan with h0 = 0, write final [B][T][D]
    init_layer1<<<(HH * BB + 255) / 256, 256>>>();
    gemm_kernel<<<dim3(8, 128), 256>>>(nullptr, 1, DD, BB * DD); // out0 rows m = t*B+b
    scan_kernel<<<NCTA, 256>>>(1, out);
}

// round 2
// speedup vs baseline: 1.0233x; 1.0233x over previous
#include <cuda_runtime.h>

#define BB   64      // batch
#define TT   256     // time
#define DD   512     // input dim
#define HH   512     // hidden dim
#define NCOL 1024    // output cols per step = H (h_new) + D (o)
#define NCTA 128     // scan grid
#define CPC  8       // columns per CTA in scan

// ---------------- scratch (static device allocations only) ----------------
__device__ __align__(16) float g_P[(size_t)TT * BB * NCOL];    // x-part preactivations
__device__ __align__(16) float g_out0[(size_t)TT * BB * DD];   // layer0 output, row m = t*B+b
__device__ __align__(16) float g_hT[2][HH][BB];                // transposed hidden, double buffered
__device__ __align__(16) float g_W0x[DD * NCOL];
__device__ __align__(16) float g_W0r[HH * NCOL];
__device__ __align__(16) float g_W1x[DD * NCOL];
__device__ __align__(16) float g_W1r[HH * NCOL];
__device__ float g_b0[NCOL];
__device__ float g_b1[NCOL];
__device__ unsigned int g_bar;

// packed fp32x2 FMA (sm_103a; ptxas never auto-fuses this — PTX only)
__device__ __forceinline__ unsigned long long ffma2(unsigned long long a,
                                                    unsigned long long b,
                                                    unsigned long long c) {
    unsigned long long d;
    asm("fma.rn.f32x2 %0, %1, %2, %3;" : "=l"(d) : "l"(a), "l"(b), "l"(c));
    return d;
}

// Accurate tanh independent of --use_fast_math (expm1f is not fast-mathed).
__device__ __forceinline__ float tanh_acc(float x) {
    float ax = fabsf(x);
    float u  = expm1f(-2.0f * ax);      // in [-1, 0]
    float r  = -u / (2.0f + u);
    return x >= 0.0f ? r : -r;
}

// ---------------- weight packing: W = [Wh | Wo], split x-rows / h-rows ----
__global__ void pack_weights(const float* __restrict__ Wh0, const float* __restrict__ Wo0,
                             const float* __restrict__ bh0, const float* __restrict__ bo0,
                             const float* __restrict__ Wh1, const float* __restrict__ Wo1,
                             const float* __restrict__ bh1, const float* __restrict__ bo1)
{
    int idx = blockIdx.x * blockDim.x + threadIdx.x;
    if (idx >= DD * NCOL) return;
    int k = idx >> 10;
    int n = idx & (NCOL - 1);
    bool hcol = (n < HH);
    int c = hcol ? n : n - HH;
    g_W0x[idx] = hcol ? Wh0[k * HH + c]        : Wo0[k * DD + c];
    g_W0r[idx] = hcol ? Wh0[(DD + k) * HH + c] : Wo0[(DD + k) * DD + c];
    g_W1x[idx] = hcol ? Wh1[k * HH + c]        : Wo1[k * DD + c];
    g_W1r[idx] = hcol ? Wh1[(DD + k) * HH + c] : Wo1[(DD + k) * DD + c];
    if (idx < NCOL) {
        g_b0[idx] = hcol ? bh0[c] : bo0[c];
        g_b1[idx] = hcol ? bh1[c] : bo1[c];
    }
}

// ---------------- per-layer init (also resets the grid barrier) ----------
__global__ void init_layer0(const float* __restrict__ enc) {
    int idx = blockIdx.x * blockDim.x + threadIdx.x;
    if (idx < HH * BB) {
        int k = idx >> 6, b = idx & 63;
        g_hT[0][k][b] = enc[b * HH + k];   // transpose encoder_output [B,H] -> [H,B]
    }
    if (idx == 0) g_bar = 0u;
}

__global__ void init_layer1() {
    int idx = blockIdx.x * blockDim.x + threadIdx.x;
    if (idx < HH * BB) g_hT[0][idx >> 6][idx & 63] = 0.0f;
    if (idx == 0) g_bar = 0u;
}

// ---------------- big parallel GEMM: P[m, 0:1024] = A_row(m) @ Wx --------
// m = t*B + b ; row offset = (m%64)*sB + (m/64)*sT ; K = 512, N = 1024.
// f32x2 inner product: A staged duplicated (a,a) in SMEM, B consumed as
// natural column pairs -> 32 FFMA2 per 8x8 tile per k.
__global__ __launch_bounds__(256)
void gemm_kernel(const float* __restrict__ Ain, int layer, int sB, int sT)
{
    const float* __restrict__ A  = Ain ? Ain : g_out0;
    const float* __restrict__ Bm = layer ? g_W1x : g_W0x;
    float* __restrict__ C = g_P;

    __shared__ __align__(16) float2 As2[16][128];   // duplicated (a,a): 16 KB
    __shared__ __align__(16) float  Bs[16][128];    // 8 KB

    const int tid = threadIdx.x;
    const int m0 = blockIdx.y * 128;
    const int n0 = blockIdx.x * 128;

    const int ai = tid >> 2;            // 0..63
    const int ak = (tid & 3) << 2;      // 0,4,8,12
    const int mg0 = m0 + ai;
    const int mg1 = m0 + ai + 64;
    const float* ap0 = A + (size_t)(mg0 & 63) * sB + (size_t)(mg0 >> 6) * sT + ak;
    const float* ap1 = A + (size_t)(mg1 & 63) * sB + (size_t)(mg1 >> 6) * sT + ak;

    const int bk = tid >> 5;            // 0..7
    const int bn = (tid & 31) << 2;     // 0..124
    const float* bp = Bm + (size_t)bk * NCOL + n0 + bn;

    const int ty = tid >> 4, tx = tid & 15;

    unsigned long long acc[8][4];
#pragma unroll
    for (int i = 0; i < 8; ++i)
#pragma unroll
        for (int j = 0; j < 4; ++j) acc[i][j] = 0ull;

    for (int k0 = 0; k0 < DD; k0 += 16) {
        float4 av0 = *(const float4*)(ap0 + k0);
        float4 av1 = *(const float4*)(ap1 + k0);
        float4 bv0 = *(const float4*)(bp + (size_t)k0 * NCOL);
        float4 bv1 = *(const float4*)(bp + (size_t)(k0 + 8) * NCOL);
        __syncthreads();
        As2[ak + 0][ai] = make_float2(av0.x, av0.x);
        As2[ak + 1][ai] = make_float2(av0.y, av0.y);
        As2[ak + 2][ai] = make_float2(av0.z, av0.z);
        As2[ak + 3][ai] = make_float2(av0.w, av0.w);
        As2[ak + 0][ai + 64] = make_float2(av1.x, av1.x);
        As2[ak + 1][ai + 64] = make_float2(av1.y, av1.y);
        As2[ak + 2][ai + 64] = make_float2(av1.z, av1.z);
        As2[ak + 3][ai + 64] = make_float2(av1.w, av1.w);
        *(float4*)&Bs[bk][bn]     = bv0;
        *(float4*)&Bs[bk + 8][bn] = bv1;
        __syncthreads();
#pragma unroll
        for (int k = 0; k < 16; ++k) {
            ulonglong2 a01 = *(const ulonglong2*)&As2[k][ty * 8 + 0];
            ulonglong2 a23 = *(const ulonglong2*)&As2[k][ty * 8 + 2];
            ulonglong2 a45 = *(const ulonglong2*)&As2[k][ty * 8 + 4];
            ulonglong2 a67 = *(const ulonglong2*)&As2[k][ty * 8 + 6];
            ulonglong2 b03 = *(const ulonglong2*)&Bs[k][tx * 8 + 0];
            ulonglong2 b47 = *(const ulonglong2*)&Bs[k][tx * 8 + 4];
            unsigned long long a[8] = {a01.x, a01.y, a23.x, a23.y,
                                       a45.x, a45.y, a67.x, a67.y};
            unsigned long long b[4] = {b03.x, b03.y, b47.x, b47.y};
#pragma unroll
            for (int i = 0; i < 8; ++i)
#pragma unroll
                for (int j = 0; j < 4; ++j)
                    acc[i][j] = ffma2(a[i], b[j], acc[i][j]);
        }
    }
#pragma unroll
    for (int i = 0; i < 8; ++i) {
        float* cp = C + (size_t)(m0 + ty * 8 + i) * NCOL + n0 + tx * 8;
        *(ulonglong2*)cp       = make_ulonglong2(acc[i][0], acc[i][1]);
        *(ulonglong2*)(cp + 4) = make_ulonglong2(acc[i][2], acc[i][3]);
    }
}

// ---------------- persistent sequential scan ------------------------------
// 128 CTAs, each owns 8 columns of [h_new | o]. One global spin barrier per step.
// h kept transposed [k][row]; per lane a row-pair float2 feeds FFMA2 against
// duplicated (w,w) weight pairs from SMEM -> 8 FFMA2 per k per lane.
__global__ __launch_bounds__(256)
void scan_kernel(int layer, float* __restrict__ dout)
{
    const float* __restrict__ Wr  = layer ? g_W1r : g_W0r;
    const float* __restrict__ bia = layer ? g_b1  : g_b0;

    __shared__ __align__(16) float2 Wsd[HH * CPC];       // (w,w) duplicated: 32 KB
    __shared__ __align__(16) float  red[8 * CPC * BB];   // warp partials: 16 KB
    __shared__ float bs[CPC];

    const int tid = threadIdx.x;
    const int n0  = blockIdx.x * CPC;

    for (int idx = tid; idx < HH * CPC; idx += 256) {
        int k = idx >> 3, j = idx & 7;
        float wv = Wr[k * NCOL + n0 + j];
        Wsd[idx] = make_float2(wv, wv);
    }
    if (tid < CPC) bs[tid] = bia[n0 + tid];
    __syncthreads();

    const int w  = tid >> 5;            // warp id: owns k in [w*64, w*64+64)
    const int ln = tid & 31;            // lane: owns rows 2*ln, 2*ln+1
    const int rr = tid >> 2;            // reduce: row
    const int jp = (tid & 3) << 1;      // reduce: col pair
    const bool isH = (n0 < HH);
    const float b0v = bs[jp], b1v = bs[jp + 1];

    for (int t = 0; t < TT; ++t) {
        // prefetch the x-part preactivation early (hides DRAM/L2 latency)
        const float2 pv = *(const float2*)&g_P[((size_t)t * BB + rr) * NCOL + n0 + jp];

        const unsigned long long* __restrict__ hp =
            (const unsigned long long*)&g_hT[t & 1][0][0];
        unsigned long long acc[8];
#pragma unroll
        for (int j = 0; j < 8; ++j) acc[j] = 0ull;

        const int kb = w * 64;
#pragma unroll 8
        for (int kk = 0; kk < 64; ++kk) {
            const int k = kb + kk;
            const unsigned long long hv = hp[k * 32 + ln];   // rows (2ln, 2ln+1)
            const ulonglong2* wp = (const ulonglong2*)&Wsd[k * 8];
            ulonglong2 w01 = wp[0];
            ulonglong2 w23 = wp[1];
            ulonglong2 w45 = wp[2];
            ulonglong2 w67 = wp[3];
            acc[0] = ffma2(hv, w01.x, acc[0]);
            acc[1] = ffma2(hv, w01.y, acc[1]);
            acc[2] = ffma2(hv, w23.x, acc[2]);
            acc[3] = ffma2(hv, w23.y, acc[3]);
            acc[4] = ffma2(hv, w45.x, acc[4]);
            acc[5] = ffma2(hv, w45.y, acc[5]);
            acc[6] = ffma2(hv, w67.x, acc[6]);
            acc[7] = ffma2(hv, w67.y, acc[7]);
        }
        // acc[j] = (partial for row 2ln, partial for row 2ln+1) packed
        unsigned long long* redq = (unsigned long long*)red;
#pragma unroll
        for (int j = 0; j < 8; ++j)
            redq[(w * 8 + j) * 32 + ln] = acc[j];
        __syncthreads();

        float s0 = 0.0f, s1 = 0.0f;
#pragma unroll
        for (int ww = 0; ww < 8; ++ww) {
            s0 += red[(ww * 8 + jp)     * BB + rr];
            s1 += red[(ww * 8 + jp + 1) * BB + rr];
        }
        s0 = tanh_acc(s0 + pv.x + b0v);
        s1 = tanh_acc(s1 + pv.y + b1v);

        if (isH) {
            float* hN = &g_hT[(t + 1) & 1][0][0];
            hN[(n0 + jp)     * BB + rr] = s0;
            hN[(n0 + jp + 1) * BB + rr] = s1;
        } else {
            const int c = n0 - HH + jp;
            if (layer == 0)
                *(float2*)&g_out0[((size_t)t * BB + rr) * DD + c] = make_float2(s0, s1);
            else
                *(float2*)&dout[((size_t)rr * TT + t) * DD + c]   = make_float2(s0, s1);
        }

        __syncthreads();
        if (tid == 0) {
            __threadfence();
            atomicAdd(&g_bar, 1u);
            const unsigned int target = (unsigned int)(t + 1) * NCTA;
            while (*((volatile unsigned int*)&g_bar) < target) { }
            __threadfence();
        }
        __syncthreads();
    }
}

// ---------------- launch ---------------------------------------------------
extern "C" void kernel_launch(void* const* d_in, const int* in_sizes, int n_in,
                              void* d_out, int out_size)
{
    const float* x   = (const float*)d_in[0];
    const float* enc = (const float*)d_in[1];
    const float* Wh0 = (const float*)d_in[2];
    const float* bh0 = (const float*)d_in[3];
    const float* Wo0 = (const float*)d_in[4];
    const float* bo0 = (const float*)d_in[5];
    const float* Wh1 = (const float*)d_in[6];
    const float* bh1 = (const float*)d_in[7];
    const float* Wo1 = (const float*)d_in[8];
    const float* bo1 = (const float*)d_in[9];
    float* out = (float*)d_out;

    pack_weights<<<(DD * NCOL + 255) / 256, 256>>>(Wh0, Wo0, bh0, bo0, Wh1, Wo1, bh1, bo1);

    // Layer 0: P = x @ W0x ; scan with h0 = encoder_output
    init_layer0<<<(HH * BB + 255) / 256, 256>>>(enc);
    gemm_kernel<<<dim3(8, 128), 256>>>(x, 0, TT * DD, DD);       // x is [B][T][D]
    scan_kernel<<<NCTA, 256>>>(0, nullptr);

    // Layer 1: P = out0 @ W1x ; scan with h0 = 0, write final [B][T][D]
    init_layer1<<<(HH * BB + 255) / 256, 256>>>();
    gemm_kernel<<<dim3(8, 128), 256>>>(nullptr, 1, DD, BB * DD); // out0 rows m = t*B+b
    scan_kernel<<<NCTA, 256>>>(1, out);
}

// round 3
// speedup vs baseline: 1.0235x; 1.0002x over previous
#include <cuda_runtime.h>

#define BB   64      // batch
#define TT   256     // time
#define DD   512     // input dim
#define HH   512     // hidden dim
#define NCOL 1024    // output cols per step = H (h_new) + D (o)
#define NCTA 128     // scan grid
#define CPC  8       // columns per CTA in scan

// ---------------- scratch (static device allocations only) ----------------
__device__ __align__(16) float g_P[(size_t)TT * BB * NCOL];    // x-part preactivations
__device__ __align__(16) float g_out0[(size_t)TT * BB * DD];   // layer0 output, row m = t*B+b
__device__ __align__(16) float g_hT[2][HH][BB];                // transposed hidden, double buffered
__device__ __align__(16) float g_W0x[DD * NCOL];
__device__ __align__(16) float g_W0r[HH * NCOL];
__device__ __align__(16) float g_W1x[DD * NCOL];
__device__ __align__(16) float g_W1r[HH * NCOL];
__device__ float g_b0[NCOL];
__device__ float g_b1[NCOL];
__device__ unsigned int g_bar;

// packed fp32x2 FMA (sm_103a; ptxas never auto-fuses this — PTX only)
__device__ __forceinline__ unsigned long long ffma2(unsigned long long a,
                                                    unsigned long long b,
                                                    unsigned long long c) {
    unsigned long long d;
    asm("fma.rn.f32x2 %0, %1, %2, %3;" : "=l"(d) : "l"(a), "l"(b), "l"(c));
    return d;
}

// Accurate tanh independent of --use_fast_math (expm1f is not fast-mathed).
__device__ __forceinline__ float tanh_acc(float x) {
    float ax = fabsf(x);
    float u  = expm1f(-2.0f * ax);      // in [-1, 0]
    float r  = -u / (2.0f + u);
    return x >= 0.0f ? r : -r;
}

// ---------------- weight packing: W = [Wh | Wo], split x-rows / h-rows ----
__global__ void pack_weights(const float* __restrict__ Wh0, const float* __restrict__ Wo0,
                             const float* __restrict__ bh0, const float* __restrict__ bo0,
                             const float* __restrict__ Wh1, const float* __restrict__ Wo1,
                             const float* __restrict__ bh1, const float* __restrict__ bo1)
{
    int idx = blockIdx.x * blockDim.x + threadIdx.x;
    if (idx >= DD * NCOL) return;
    int k = idx >> 10;
    int n = idx & (NCOL - 1);
    bool hcol = (n < HH);
    int c = hcol ? n : n - HH;
    g_W0x[idx] = hcol ? Wh0[k * HH + c]        : Wo0[k * DD + c];
    g_W0r[idx] = hcol ? Wh0[(DD + k) * HH + c] : Wo0[(DD + k) * DD + c];
    g_W1x[idx] = hcol ? Wh1[k * HH + c]        : Wo1[k * DD + c];
    g_W1r[idx] = hcol ? Wh1[(DD + k) * HH + c] : Wo1[(DD + k) * DD + c];
    if (idx < NCOL) {
        g_b0[idx] = hcol ? bh0[c] : bo0[c];
        g_b1[idx] = hcol ? bh1[c] : bo1[c];
    }
}

// ---------------- per-layer init (also resets the grid barrier) ----------
__global__ void init_layer0(const float* __restrict__ enc) {
    int idx = blockIdx.x * blockDim.x + threadIdx.x;
    if (idx < HH * BB) {
        int k = idx >> 6, b = idx & 63;
        g_hT[0][k][b] = enc[b * HH + k];   // transpose encoder_output [B,H] -> [H,B]
    }
    if (idx == 0) g_bar = 0u;
}

__global__ void init_layer1() {
    int idx = blockIdx.x * blockDim.x + threadIdx.x;
    if (idx < HH * BB) g_hT[0][idx >> 6][idx & 63] = 0.0f;
    if (idx == 0) g_bar = 0u;
}

// ---------------- big parallel GEMM: P[m, 0:1024] = A_row(m) @ Wx --------
// m = t*B + b ; row offset = (m%64)*sB + (m/64)*sT ; K = 512, N = 1024.
// f32x2 inner product: A staged duplicated (a,a) in SMEM, B consumed as
// natural column pairs -> 32 FFMA2 per 8x8 tile per k.
__global__ __launch_bounds__(256)
void gemm_kernel(const float* __restrict__ Ain, int layer, int sB, int sT)
{
    const float* __restrict__ A  = Ain ? Ain : g_out0;
    const float* __restrict__ Bm = layer ? g_W1x : g_W0x;
    float* __restrict__ C = g_P;

    __shared__ __align__(16) float2 As2[16][128];   // duplicated (a,a): 16 KB
    __shared__ __align__(16) float  Bs[16][128];    // 8 KB

    const int tid = threadIdx.x;
    const int m0 = blockIdx.y * 128;
    const int n0 = blockIdx.x * 128;

    const int ai = tid >> 2;            // 0..63
    const int ak = (tid & 3) << 2;      // 0,4,8,12
    const int mg0 = m0 + ai;
    const int mg1 = m0 + ai + 64;
    const float* ap0 = A + (size_t)(mg0 & 63) * sB + (size_t)(mg0 >> 6) * sT + ak;
    const float* ap1 = A + (size_t)(mg1 & 63) * sB + (size_t)(mg1 >> 6) * sT + ak;

    const int bk = tid >> 5;            // 0..7
    const int bn = (tid & 31) << 2;     // 0..124
    const float* bp = Bm + (size_t)bk * NCOL + n0 + bn;

    const int ty = tid >> 4, tx = tid & 15;

    unsigned long long acc[8][4];
#pragma unroll
    for (int i = 0; i < 8; ++i)
#pragma unroll
        for (int j = 0; j < 4; ++j) acc[i][j] = 0ull;

    for (int k0 = 0; k0 < DD; k0 += 16) {
        float4 av0 = *(const float4*)(ap0 + k0);
        float4 av1 = *(const float4*)(ap1 + k0);
        float4 bv0 = *(const float4*)(bp + (size_t)k0 * NCOL);
        float4 bv1 = *(const float4*)(bp + (size_t)(k0 + 8) * NCOL);
        __syncthreads();
        As2[ak + 0][ai] = make_float2(av0.x, av0.x);
        As2[ak + 1][ai] = make_float2(av0.y, av0.y);
        As2[ak + 2][ai] = make_float2(av0.z, av0.z);
        As2[ak + 3][ai] = make_float2(av0.w, av0.w);
        As2[ak + 0][ai + 64] = make_float2(av1.x, av1.x);
        As2[ak + 1][ai + 64] = make_float2(av1.y, av1.y);
        As2[ak + 2][ai + 64] = make_float2(av1.z, av1.z);
        As2[ak + 3][ai + 64] = make_float2(av1.w, av1.w);
        *(float4*)&Bs[bk][bn]     = bv0;
        *(float4*)&Bs[bk + 8][bn] = bv1;
        __syncthreads();
#pragma unroll
        for (int k = 0; k < 16; ++k) {
            ulonglong2 a01 = *(const ulonglong2*)&As2[k][ty * 8 + 0];
            ulonglong2 a23 = *(const ulonglong2*)&As2[k][ty * 8 + 2];
            ulonglong2 a45 = *(const ulonglong2*)&As2[k][ty * 8 + 4];
            ulonglong2 a67 = *(const ulonglong2*)&As2[k][ty * 8 + 6];
            ulonglong2 b03 = *(const ulonglong2*)&Bs[k][tx * 8 + 0];
            ulonglong2 b47 = *(const ulonglong2*)&Bs[k][tx * 8 + 4];
            unsigned long long a[8] = {a01.x, a01.y, a23.x, a23.y,
                                       a45.x, a45.y, a67.x, a67.y};
            unsigned long long b[4] = {b03.x, b03.y, b47.x, b47.y};
#pragma unroll
            for (int i = 0; i < 8; ++i)
#pragma unroll
                for (int j = 0; j < 4; ++j)
                    acc[i][j] = ffma2(a[i], b[j], acc[i][j]);
        }
    }
#pragma unroll
    for (int i = 0; i < 8; ++i) {
        float* cp = C + (size_t)(m0 + ty * 8 + i) * NCOL + n0 + tx * 8;
        *(ulonglong2*)cp       = make_ulonglong2(acc[i][0], acc[i][1]);
        *(ulonglong2*)(cp + 4) = make_ulonglong2(acc[i][2], acc[i][3]);
    }
}

// ---------------- persistent sequential scan ------------------------------
// 128 CTAs, each owns 8 columns of [h_new | o]. One global spin barrier per step.
// h kept transposed [k][row]; per lane a row-pair float2 feeds FFMA2 against
// duplicated (w,w) weight pairs from SMEM -> 8 FFMA2 per k per lane.
__global__ __launch_bounds__(256)
void scan_kernel(int layer, float* __restrict__ dout)
{
    const float* __restrict__ Wr  = layer ? g_W1r : g_W0r;
    const float* __restrict__ bia = layer ? g_b1  : g_b0;

    __shared__ __align__(16) float2 Wsd[HH * CPC];       // (w,w) duplicated: 32 KB
    __shared__ __align__(16) float  red[8 * CPC * BB];   // warp partials: 16 KB
    __shared__ float bs[CPC];

    const int tid = threadIdx.x;
    const int n0  = blockIdx.x * CPC;

    for (int idx = tid; idx < HH * CPC; idx += 256) {
        int k = idx >> 3, j = idx & 7;
        float wv = Wr[k * NCOL + n0 + j];
        Wsd[idx] = make_float2(wv, wv);
    }
    if (tid < CPC) bs[tid] = bia[n0 + tid];
    __syncthreads();

    const int w  = tid >> 5;            // warp id: owns k in [w*64, w*64+64)
    const int ln = tid & 31;            // lane: owns rows 2*ln, 2*ln+1
    const int rr = tid >> 2;            // reduce: row
    const int jp = (tid & 3) << 1;      // reduce: col pair
    const bool isH = (n0 < HH);
    const float b0v = bs[jp], b1v = bs[jp + 1];

    for (int t = 0; t < TT; ++t) {
        // prefetch the x-part preactivation early (hides DRAM/L2 latency)
        const float2 pv = *(const float2*)&g_P[((size_t)t * BB + rr) * NCOL + n0 + jp];

        const unsigned long long* __restrict__ hp =
            (const unsigned long long*)&g_hT[t & 1][0][0];
        unsigned long long acc[8];
#pragma unroll
        for (int j = 0; j < 8; ++j) acc[j] = 0ull;

        const int kb = w * 64;
#pragma unroll 8
        for (int kk = 0; kk < 64; ++kk) {
            const int k = kb + kk;
            const unsigned long long hv = hp[k * 32 + ln];   // rows (2ln, 2ln+1)
            const ulonglong2* wp = (const ulonglong2*)&Wsd[k * 8];
            ulonglong2 w01 = wp[0];
            ulonglong2 w23 = wp[1];
            ulonglong2 w45 = wp[2];
            ulonglong2 w67 = wp[3];
            acc[0] = ffma2(hv, w01.x, acc[0]);
            acc[1] = ffma2(hv, w01.y, acc[1]);
            acc[2] = ffma2(hv, w23.x, acc[2]);
            acc[3] = ffma2(hv, w23.y, acc[3]);
            acc[4] = ffma2(hv, w45.x, acc[4]);
            acc[5] = ffma2(hv, w45.y, acc[5]);
            acc[6] = ffma2(hv, w67.x, acc[6]);
            acc[7] = ffma2(hv, w67.y, acc[7]);
        }
        // acc[j] = (partial for row 2ln, partial for row 2ln+1) packed
        unsigned long long* redq = (unsigned long long*)red;
#pragma unroll
        for (int j = 0; j < 8; ++j)
            redq[(w * 8 + j) * 32 + ln] = acc[j];
        __syncthreads();

        float s0 = 0.0f, s1 = 0.0f;
#pragma unroll
        for (int ww = 0; ww < 8; ++ww) {
            s0 += red[(ww * 8 + jp)     * BB + rr];
            s1 += red[(ww * 8 + jp + 1) * BB + rr];
        }
        s0 = tanh_acc(s0 + pv.x + b0v);
        s1 = tanh_acc(s1 + pv.y + b1v);

        if (isH) {
            float* hN = &g_hT[(t + 1) & 1][0][0];
            hN[(n0 + jp)     * BB + rr] = s0;
            hN[(n0 + jp + 1) * BB + rr] = s1;
        } else {
            const int c = n0 - HH + jp;
            if (layer == 0)
                *(float2*)&g_out0[((size_t)t * BB + rr) * DD + c] = make_float2(s0, s1);
            else
                *(float2*)&dout[((size_t)rr * TT + t) * DD + c]   = make_float2(s0, s1);
        }

        __syncthreads();
        if (tid == 0) {
            __threadfence();
            atomicAdd(&g_bar, 1u);
            const unsigned int target = (unsigned int)(t + 1) * NCTA;
            while (*((volatile unsigned int*)&g_bar) < target) { }
            __threadfence();
        }
        __syncthreads();
    }
}

// ---------------- launch ---------------------------------------------------
extern "C" void kernel_launch(void* const* d_in, const int* in_sizes, int n_in,
                              void* d_out, int out_size)
{
    const float* x   = (const float*)d_in[0];
    const float* enc = (const float*)d_in[1];
    const float* Wh0 = (const float*)d_in[2];
    const float* bh0 = (const float*)d_in[3];
    const float* Wo0 = (const float*)d_in[4];
    const float* bo0 = (const float*)d_in[5];
    const float* Wh1 = (const float*)d_in[6];
    const float* bh1 = (const float*)d_in[7];
    const float* Wo1 = (const float*)d_in[8];
    const float* bo1 = (const float*)d_in[9];
    float* out = (float*)d_out;

    pack_weights<<<(DD * NCOL + 255) / 256, 256>>>(Wh0, Wo0, bh0, bo0, Wh1, Wo1, bh1, bo1);

    // Layer 0: P = x @ W0x ; scan with h0 = encoder_output
    init_layer0<<<(HH * BB + 255) / 256, 256>>>(enc);
    gemm_kernel<<<dim3(8, 128), 256>>>(x, 0, TT * DD, DD);       // x is [B][T][D]
    scan_kernel<<<NCTA, 256>>>(0, nullptr);

    // Layer 1: P = out0 @ W1x ; scan with h0 = 0, write final [B][T][D]
    init_layer1<<<(HH * BB + 255) / 256, 256>>>();
    gemm_kernel<<<dim3(8, 128), 256>>>(nullptr, 1, DD, BB * DD); // out0 rows m = t*B+b
    scan_kernel<<<NCTA, 256>>>(1, out);
}

// round 4
// speedup vs baseline: 1.1672x; 1.1404x over previous
#include <cuda_runtime.h>

#define BB 64
#define TT 256
#define DD 512
#define HH 512

typedef unsigned long long ull;

// ---------------- scratch (static device allocations only) ----------------
__device__ __align__(16) float g_h0T[2][HH * BB];        // h0 [k][b], double buffered
__device__ __align__(16) float g_o0T[TT][DD * BB];       // o0_t [k][b] history (32 MB)
__device__ __align__(16) float g_h1T[TT][HH * BB];       // g_h1T[t] = h1_{t-1} (32 MB)
__device__ __align__(16) float g_P0[(size_t)TT * BB * 1024]; // x @ W0x (64 MB)
__device__ __align__(16) float g_W0x[DD * 1024];
__device__ __align__(16) float g_W0r[HH * 1024];
__device__ float g_b0[1024];
__device__ unsigned int g_bar;

// ---------------- helpers --------------------------------------------------
__device__ __forceinline__ ull ffma2(ull a, ull b, ull c) {
    ull d; asm("fma.rn.f32x2 %0, %1, %2, %3;" : "=l"(d) : "l"(a), "l"(b), "l"(c));
    return d;
}
__device__ __forceinline__ ull dup2(float x) {
    ull d; asm("mov.b64 %0, {%1, %1};" : "=l"(d) : "f"(x));
    return d;
}
__device__ __forceinline__ float2 unpk(ull a) {
    float2 v; asm("mov.b64 {%0, %1}, %2;" : "=f"(v.x), "=f"(v.y) : "l"(a));
    return v;
}
__device__ __forceinline__ float2 ldcg2(const float* p) {
    float2 v;
    asm volatile("ld.global.cg.v2.f32 {%0,%1}, [%2];" : "=f"(v.x), "=f"(v.y) : "l"(p));
    return v;
}
__device__ __forceinline__ void stcg(float* p, float v) {
    asm volatile("st.global.cg.f32 [%0], %1;" :: "l"(p), "f"(v));
}
// Accurate tanh independent of --use_fast_math.
__device__ __forceinline__ float tanh_acc(float x) {
    float ax = fabsf(x);
    float u  = expm1f(-2.0f * ax);
    float r  = -u / (2.0f + u);
    return x >= 0.0f ? r : -r;
}

// ---------------- layer-0 weight packing ----------------------------------
__global__ void pack0(const float* __restrict__ Wh0, const float* __restrict__ Wo0,
                      const float* __restrict__ bh0, const float* __restrict__ bo0)
{
    int idx = blockIdx.x * blockDim.x + threadIdx.x;
    if (idx >= DD * 1024) return;
    int k = idx >> 10, n = idx & 1023;
    bool hc = n < HH;
    int c = hc ? n : n - HH;
    g_W0x[idx] = hc ? Wh0[k * HH + c]        : Wo0[k * DD + c];
    g_W0r[idx] = hc ? Wh0[(DD + k) * HH + c] : Wo0[(DD + k) * DD + c];
    if (idx < 1024) g_b0[idx] = hc ? bh0[c] : bo0[c];
}

__global__ void init_state(const float* __restrict__ enc) {
    int idx = blockIdx.x * blockDim.x + threadIdx.x;
    if (idx < HH * BB) {
        int k = idx >> 6, b = idx & 63;
        g_h0T[0][k * 64 + b] = enc[b * HH + k];  // transpose [B,H] -> [H,B]
        g_h1T[0][idx] = 0.0f;                    // h1_{-1} = 0
    }
    if (idx == 0) g_bar = 0u;
}

// ---------------- GEMM 0: P0[m,0:1024] = x_row(m) @ W0x,  m = t*64+b -------
__global__ __launch_bounds__(256)
void gemm0(const float* __restrict__ x)
{
    __shared__ __align__(16) float2 As2[16][128];
    __shared__ __align__(16) float  Bs[16][128];

    const int tid = threadIdx.x;
    const int m0 = blockIdx.y * 128;
    const int n0 = blockIdx.x * 128;

    const int ai = tid >> 2;
    const int ak = (tid & 3) << 2;
    const int mg0 = m0 + ai, mg1 = m0 + ai + 64;
    const float* ap0 = x + (size_t)(mg0 & 63) * (TT * DD) + (size_t)(mg0 >> 6) * DD + ak;
    const float* ap1 = x + (size_t)(mg1 & 63) * (TT * DD) + (size_t)(mg1 >> 6) * DD + ak;

    const int bk = tid >> 5;
    const int bn = (tid & 31) << 2;
    const float* bp = g_W0x + (size_t)bk * 1024 + n0 + bn;

    const int ty = tid >> 4, tx = tid & 15;

    ull acc[8][4];
#pragma unroll
    for (int i = 0; i < 8; ++i)
#pragma unroll
        for (int j = 0; j < 4; ++j) acc[i][j] = 0ull;

    for (int k0 = 0; k0 < DD; k0 += 16) {
        float4 av0 = *(const float4*)(ap0 + k0);
        float4 av1 = *(const float4*)(ap1 + k0);
        float4 bv0 = *(const float4*)(bp + (size_t)k0 * 1024);
        float4 bv1 = *(const float4*)(bp + (size_t)(k0 + 8) * 1024);
        __syncthreads();
        As2[ak + 0][ai] = make_float2(av0.x, av0.x);
        As2[ak + 1][ai] = make_float2(av0.y, av0.y);
        As2[ak + 2][ai] = make_float2(av0.z, av0.z);
        As2[ak + 3][ai] = make_float2(av0.w, av0.w);
        As2[ak + 0][ai + 64] = make_float2(av1.x, av1.x);
        As2[ak + 1][ai + 64] = make_float2(av1.y, av1.y);
        As2[ak + 2][ai + 64] = make_float2(av1.z, av1.z);
        As2[ak + 3][ai + 64] = make_float2(av1.w, av1.w);
        *(float4*)&Bs[bk][bn]     = bv0;
        *(float4*)&Bs[bk + 8][bn] = bv1;
        __syncthreads();
#pragma unroll
        for (int k = 0; k < 16; ++k) {
            ulonglong2 a01 = *(const ulonglong2*)&As2[k][ty * 8 + 0];
            ulonglong2 a23 = *(const ulonglong2*)&As2[k][ty * 8 + 2];
            ulonglong2 a45 = *(const ulonglong2*)&As2[k][ty * 8 + 4];
            ulonglong2 a67 = *(const ulonglong2*)&As2[k][ty * 8 + 6];
            ulonglong2 b03 = *(const ulonglong2*)&Bs[k][tx * 8 + 0];
            ulonglong2 b47 = *(const ulonglong2*)&Bs[k][tx * 8 + 4];
            ull a[8] = {a01.x, a01.y, a23.x, a23.y, a45.x, a45.y, a67.x, a67.y};
            ull b[4] = {b03.x, b03.y, b47.x, b47.y};
#pragma unroll
            for (int i = 0; i < 8; ++i)
#pragma unroll
                for (int j = 0; j < 4; ++j)
                    acc[i][j] = ffma2(a[i], b[j], acc[i][j]);
        }
    }
#pragma unroll
    for (int i = 0; i < 8; ++i) {
        float* cp = g_P0 + (size_t)(m0 + ty * 8 + i) * 1024 + n0 + tx * 8;
        *(ulonglong2*)cp       = make_ulonglong2(acc[i][0], acc[i][1]);
        *(ulonglong2*)(cp + 4) = make_ulonglong2(acc[i][2], acc[i][3]);
    }
}

// ---------------- fused pipelined scan -------------------------------------
// bx < 64  : "A" CTA — 16 cols of [h0|o0], K=512 vs g_h0T
// bx >= 64 : "B" CTA — 8 cols of h1, K=1024 vs [o0_{t-1} | h1_{t-2}]
// 255 global barrier rounds (release/acquire, .cg data path, no L1 flush).
__global__ __launch_bounds__(256)
void scan_fused(const float* __restrict__ Wh1, const float* __restrict__ bh1)
{
    extern __shared__ float sm[];
    float* Ws  = sm;          // 8192 floats = 32 KB
    float* red = sm + 8192;   // 4096 floats = 16 KB

    const int tid = threadIdx.x;
    const int bx  = blockIdx.x;
    const int w   = tid >> 5, ln = tid & 31;
    const int rr  = tid >> 2;             // reduce row (0..63)
    const int jj  = (tid & 3) << 1;       // reduce col pair base (0,2,4,6)
    const ull* wsq = (const ull*)Ws;
    ull* redq = (ull*)red;

    if (bx < 64) {
        // ================= A: layer-0 recurrent part =================
        const int n0 = bx * 16;
        for (int i = tid; i < 512 * 16; i += 256) {
            int k = i >> 4, j = i & 15;
            Ws[i] = g_W0r[k * 1024 + n0 + j];
        }
        float bA00 = g_b0[n0 + jj],     bA01 = g_b0[n0 + jj + 1];
        float bA10 = g_b0[n0 + 8 + jj], bA11 = g_b0[n0 + 8 + jj + 1];
        __syncthreads();

        const int kb = w * 64;
        for (int r = 0; r < TT; ++r) {
            float2 p0 = ldcg2(&g_P0[((size_t)r * 64 + rr) * 1024 + n0 + jj]);
            float2 p1 = ldcg2(&g_P0[((size_t)r * 64 + rr) * 1024 + n0 + 8 + jj]);
            const float* hsrc = g_h0T[r & 1];

            ull a0[8], a1[8];
#pragma unroll
            for (int q = 0; q < 8; ++q) { a0[q] = 0ull; a1[q] = 0ull; }
#pragma unroll 4
            for (int kk = 0; kk < 64; ++kk) {
                const int k = kb + kk;
                float2 h2 = ldcg2(hsrc + k * 64 + 2 * ln);
                ull hx = dup2(h2.x), hy = dup2(h2.y);
                const ulonglong2* wp = (const ulonglong2*)(wsq + (size_t)k * 8);
                ulonglong2 u0 = wp[0], u1 = wp[1], u2 = wp[2], u3 = wp[3];
                a0[0] = ffma2(hx, u0.x, a0[0]); a1[0] = ffma2(hy, u0.x, a1[0]);
                a0[1] = ffma2(hx, u0.y, a0[1]); a1[1] = ffma2(hy, u0.y, a1[1]);
                a0[2] = ffma2(hx, u1.x, a0[2]); a1[2] = ffma2(hy, u1.x, a1[2]);
                a0[3] = ffma2(hx, u1.y, a0[3]); a1[3] = ffma2(hy, u1.y, a1[3]);
                a0[4] = ffma2(hx, u2.x, a0[4]); a1[4] = ffma2(hy, u2.x, a1[4]);
                a0[5] = ffma2(hx, u2.y, a0[5]); a1[5] = ffma2(hy, u2.y, a1[5]);
                a0[6] = ffma2(hx, u3.x, a0[6]); a1[6] = ffma2(hy, u3.x, a1[6]);
                a0[7] = ffma2(hx, u3.y, a0[7]); a1[7] = ffma2(hy, u3.y, a1[7]);
            }
            // two reduce passes of 8 cols each (red = 16 KB)
#pragma unroll
            for (int p = 0; p < 2; ++p) {
#pragma unroll
                for (int q = 0; q < 4; ++q) {
                    redq[(w * 64 + 2 * ln)     * 4 + q] = a0[p * 4 + q];
                    redq[(w * 64 + 2 * ln + 1) * 4 + q] = a1[p * 4 + q];
                }
                __syncthreads();
                float s0 = (p ? p1.x : p0.x) + (p ? bA10 : bA00);
                float s1 = (p ? p1.y : p0.y) + (p ? bA11 : bA01);
#pragma unroll
                for (int ww = 0; ww < 8; ++ww) {
                    float2 t2 = *(const float2*)&red[(ww * 64 + rr) * 8 + jj];
                    s0 += t2.x; s1 += t2.y;
                }
                s0 = tanh_acc(s0);
                s1 = tanh_acc(s1);
                const int c = n0 + p * 8 + jj;
                if (n0 < 512) {
                    float* dst = g_h0T[(r + 1) & 1];
                    stcg(dst + (c)     * 64 + rr, s0);
                    stcg(dst + (c + 1) * 64 + rr, s1);
                } else {
                    float* dst = g_o0T[r];
                    stcg(dst + (c - 512) * 64 + rr, s0);
                    stcg(dst + (c - 511) * 64 + rr, s1);
                }
                __syncthreads();
            }
            if (r < TT - 1) {
                if (tid == 0) {
                    asm volatile("red.release.gpu.global.add.u32 [%0], 1;"
                                 :: "l"(&g_bar) : "memory");
                    const unsigned tgt = (unsigned)(r + 1) * 128u;
                    unsigned v;
                    do {
                        asm volatile("ld.acquire.gpu.global.u32 %0, [%1];"
                                     : "=r"(v) : "l"(&g_bar) : "memory");
                    } while (v < tgt);
                }
                __syncthreads();
            }
        }
    } else {
        // ================= B: layer-1 hidden chain (one step behind) =========
        const int c0 = (bx - 64) * 8;
        for (int i = tid; i < 1024 * 8; i += 256) {
            int k = i >> 3, j = i & 7;
            Ws[i] = Wh1[k * 512 + c0 + j];
        }
        const float b0v = bh1[c0 + jj], b1v = bh1[c0 + jj + 1];
        __syncthreads();

        const int kb = w * 128;                       // k in [kb, kb+128)
        for (int r = 0; r < TT; ++r) {
            if (r >= 1) {
                const int t1 = r - 1;                  // computing h1_{t1}
                const float* src = (w < 4)
                    ? (g_o0T[t1] + (size_t)kb * 64)            // o0_{t1}, k<512
                    : (g_h1T[t1] + (size_t)(kb - 512) * 64);   // h1_{t1-1}
                ull a0[4], a1[4];
#pragma unroll
                for (int q = 0; q < 4; ++q) { a0[q] = 0ull; a1[q] = 0ull; }
#pragma unroll 4
                for (int kk = 0; kk < 128; ++kk) {
                    float2 h2 = ldcg2(src + (size_t)kk * 64 + 2 * ln);
                    ull hx = dup2(h2.x), hy = dup2(h2.y);
                    const ulonglong2* wp = (const ulonglong2*)(wsq + (size_t)(kb + kk) * 4);
                    ulonglong2 u0 = wp[0], u1 = wp[1];
                    a0[0] = ffma2(hx, u0.x, a0[0]); a1[0] = ffma2(hy, u0.x, a1[0]);
                    a0[1] = ffma2(hx, u0.y, a0[1]); a1[1] = ffma2(hy, u0.y, a1[1]);
                    a0[2] = ffma2(hx, u1.x, a0[2]); a1[2] = ffma2(hy, u1.x, a1[2]);
                    a0[3] = ffma2(hx, u1.y, a0[3]); a1[3] = ffma2(hy, u1.y, a1[3]);
                }
#pragma unroll
                for (int q = 0; q < 4; ++q) {
                    redq[(w * 64 + 2 * ln)     * 4 + q] = a0[q];
                    redq[(w * 64 + 2 * ln + 1) * 4 + q] = a1[q];
                }
                __syncthreads();
                float s0 = b0v, s1 = b1v;
#pragma unroll
                for (int ww = 0; ww < 8; ++ww) {
                    float2 t2 = *(const float2*)&red[(ww * 64 + rr) * 8 + jj];
                    s0 += t2.x; s1 += t2.y;
                }
                s0 = tanh_acc(s0);
                s1 = tanh_acc(s1);
                // store h1_{t1} into g_h1T[t1+1] (only needed for t1 <= 254)
                if (r < TT) {
                    float* dst = g_h1T[r];
                    stcg(dst + (c0 + jj)     * 64 + rr, s0);
                    stcg(dst + (c0 + jj + 1) * 64 + rr, s1);
                }
                __syncthreads();
            }
            if (r < TT - 1) {
                if (tid == 0) {
                    asm volatile("red.release.gpu.global.add.u32 [%0], 1;"
                                 :: "l"(&g_bar) : "memory");
                    const unsigned tgt = (unsigned)(r + 1) * 128u;
                    unsigned v;
                    do {
                        asm volatile("ld.acquire.gpu.global.u32 %0, [%1];"
                                     : "=r"(v) : "l"(&g_bar) : "memory");
                    } while (v < tgt);
                }
                __syncthreads();
            }
        }
    }
}

// ---------------- GEMM 1: out = tanh([o0_t | h1_{t-1}] @ Wo1 + bo1) --------
// M = 16384 (m = t*64+b), N = 512, K = 1024. A read transposed from histories.
__global__ __launch_bounds__(256)
void gemm1(const float* __restrict__ Wo1, const float* __restrict__ bo1,
           float* __restrict__ out)
{
    __shared__ __align__(16) float2 As2[16][128];
    __shared__ __align__(16) float  Bs[16][128];

    const int tid = threadIdx.x;
    const int m0 = blockIdx.y * 128;
    const int n0 = blockIdx.x * 128;

    const int kk = tid >> 5;             // 0..7
    const int mm = (tid & 31) << 2;      // 0..124
    const int t  = (m0 >> 6) + (mm >> 6);
    const int b  = mm & 63;
    const size_t aoff = (size_t)t * (512 * 64) + b;

    const int bk = tid >> 5;
    const int bn = (tid & 31) << 2;

    const int ty = tid >> 4, tx = tid & 15;

    ull acc[8][4];
#pragma unroll
    for (int i = 0; i < 8; ++i)
#pragma unroll
        for (int j = 0; j < 4; ++j) acc[i][j] = 0ull;

    for (int k0 = 0; k0 < 1024; k0 += 16) {
        const float* Abase = (k0 < 512) ? &g_o0T[0][0] : &g_h1T[0][0];
        const int koff = (k0 < 512) ? k0 : (k0 - 512);
        float4 av0 = *(const float4*)(Abase + aoff + (size_t)(koff + kk) * 64);
        float4 av1 = *(const float4*)(Abase + aoff + (size_t)(koff + kk + 8) * 64);
        float4 bv0 = *(const float4*)(Wo1 + (size_t)(k0 + bk) * 512 + n0 + bn);
        float4 bv1 = *(const float4*)(Wo1 + (size_t)(k0 + bk + 8) * 512 + n0 + bn);
        __syncthreads();
        As2[kk][mm + 0] = make_float2(av0.x, av0.x);
        As2[kk][mm + 1] = make_float2(av0.y, av0.y);
        As2[kk][mm + 2] = make_float2(av0.z, av0.z);
        As2[kk][mm + 3] = make_float2(av0.w, av0.w);
        As2[kk + 8][mm + 0] = make_float2(av1.x, av1.x);
        As2[kk + 8][mm + 1] = make_float2(av1.y, av1.y);
        As2[kk + 8][mm + 2] = make_float2(av1.z, av1.z);
        As2[kk + 8][mm + 3] = make_float2(av1.w, av1.w);
        *(float4*)&Bs[bk][bn]     = bv0;
        *(float4*)&Bs[bk + 8][bn] = bv1;
        __syncthreads();
#pragma unroll
        for (int k = 0; k < 16; ++k) {
            ulonglong2 a01 = *(const ulonglong2*)&As2[k][ty * 8 + 0];
            ulonglong2 a23 = *(const ulonglong2*)&As2[k][ty * 8 + 2];
            ulonglong2 a45 = *(const ulonglong2*)&As2[k][ty * 8 + 4];
            ulonglong2 a67 = *(const ulonglong2*)&As2[k][ty * 8 + 6];
            ulonglong2 b03 = *(const ulonglong2*)&Bs[k][tx * 8 + 0];
            ulonglong2 b47 = *(const ulonglong2*)&Bs[k][tx * 8 + 4];
            ull a[8] = {a01.x, a01.y, a23.x, a23.y, a45.x, a45.y, a67.x, a67.y};
            ull b2[4] = {b03.x, b03.y, b47.x, b47.y};
#pragma unroll
            for (int i = 0; i < 8; ++i)
#pragma unroll
                for (int j = 0; j < 4; ++j)
                    acc[i][j] = ffma2(a[i], b2[j], acc[i][j]);
        }
    }

    float4 bia0 = *(const float4*)(bo1 + n0 + tx * 8);
    float4 bia1 = *(const float4*)(bo1 + n0 + tx * 8 + 4);
#pragma unroll
    for (int i = 0; i < 8; ++i) {
        const int m  = m0 + ty * 8 + i;
        const int tt = m >> 6, bb = m & 63;
        float* cp = out + ((size_t)bb * TT + tt) * 512 + n0 + tx * 8;
        float2 v0 = unpk(acc[i][0]);
        float2 v1 = unpk(acc[i][1]);
        float2 v2 = unpk(acc[i][2]);
        float2 v3 = unpk(acc[i][3]);
        float4 o0, o1;
        o0.x = tanh_acc(v0.x + bia0.x);
        o0.y = tanh_acc(v0.y + bia0.y);
        o0.z = tanh_acc(v1.x + bia0.z);
        o0.w = tanh_acc(v1.y + bia0.w);
        o1.x = tanh_acc(v2.x + bia1.x);
        o1.y = tanh_acc(v2.y + bia1.y);
        o1.z = tanh_acc(v3.x + bia1.z);
        o1.w = tanh_acc(v3.y + bia1.w);
        *(float4*)cp       = o0;
        *(float4*)(cp + 4) = o1;
    }
}

// ---------------- launch ---------------------------------------------------
extern "C" void kernel_launch(void* const* d_in, const int* in_sizes, int n_in,
                              void* d_out, int out_size)
{
    const float* x   = (const float*)d_in[0];
    const float* enc = (const float*)d_in[1];
    const float* Wh0 = (const float*)d_in[2];
    const float* bh0 = (const float*)d_in[3];
    const float* Wo0 = (const float*)d_in[4];
    const float* bo0 = (const float*)d_in[5];
    const float* Wh1 = (const float*)d_in[6];
    const float* bh1 = (const float*)d_in[7];
    const float* Wo1 = (const float*)d_in[8];
    const float* bo1 = (const float*)d_in[9];
    float* out = (float*)d_out;

    pack0<<<(DD * 1024 + 255) / 256, 256>>>(Wh0, Wo0, bh0, bo0);
    init_state<<<(HH * BB + 255) / 256, 256>>>(enc);
    gemm0<<<dim3(8, 128), 256>>>(x);
    scan_fused<<<128, 256, 49152>>>(Wh1, bh1);
    gemm1<<<dim3(4, 128), 256>>>(Wo1, bo1, out);
}

// round 5
// speedup vs baseline: 1.6339x; 1.3999x over previous
#include <cuda_runtime.h>

#define BB 64
#define TT 256
#define DD 512
#define HH 512

typedef unsigned long long ull;

// ---------------- scratch (static device allocations only) ----------------
__device__ __align__(16) float g_h0T[2][HH * BB];        // h0 [k][b], double buffered
__device__ __align__(16) float g_o0T[TT][DD * BB];       // o0_t [k][b] history
__device__ __align__(16) float g_h1T[TT][HH * BB];       // g_h1T[t] = h1_{t-1}
__device__ __align__(16) float g_P0[(size_t)TT * BB * 1024]; // x @ W0x
__device__ __align__(16) float g_W0x[DD * 1024];
__device__ __align__(16) float g_W0r[HH * 1024];
__device__ float g_b0[1024];
__device__ unsigned int g_bar;

// ---------------- helpers --------------------------------------------------
__device__ __forceinline__ ull ffma2(ull a, ull b, ull c) {
    ull d; asm("fma.rn.f32x2 %0, %1, %2, %3;" : "=l"(d) : "l"(a), "l"(b), "l"(c));
    return d;
}
__device__ __forceinline__ ull dup2(float x) {
    ull d; asm("mov.b64 %0, {%1, %1};" : "=l"(d) : "f"(x));
    return d;
}
__device__ __forceinline__ float2 unpk(ull a) {
    float2 v; asm("mov.b64 {%0, %1}, %2;" : "=f"(v.x), "=f"(v.y) : "l"(a));
    return v;
}
__device__ __forceinline__ float2 ldcg2(const float* p) {
    float2 v;
    asm volatile("ld.global.cg.v2.f32 {%0,%1}, [%2];" : "=f"(v.x), "=f"(v.y) : "l"(p));
    return v;
}
__device__ __forceinline__ void stcg(float* p, float v) {
    asm volatile("st.global.cg.f32 [%0], %1;" :: "l"(p), "f"(v));
}
// cp.async L2->SMEM, 16B
__device__ __forceinline__ void cpasync16(unsigned saddr, const float* gptr) {
    asm volatile("cp.async.cg.shared.global [%0], [%1], 16;" :: "r"(saddr), "l"(gptr));
}
__device__ __forceinline__ void cp_commit() {
    asm volatile("cp.async.commit_group;");
}
template <int N>
__device__ __forceinline__ void cp_wait() {
    asm volatile("cp.async.wait_group %0;" :: "n"(N));
}
// Accurate tanh independent of --use_fast_math.
__device__ __forceinline__ float tanh_acc(float x) {
    float ax = fabsf(x);
    float u  = expm1f(-2.0f * ax);
    float r  = -u / (2.0f + u);
    return x >= 0.0f ? r : -r;
}

// ---------------- layer-0 weight packing ----------------------------------
__global__ void pack0(const float* __restrict__ Wh0, const float* __restrict__ Wo0,
                      const float* __restrict__ bh0, const float* __restrict__ bo0)
{
    int idx = blockIdx.x * blockDim.x + threadIdx.x;
    if (idx >= DD * 1024) return;
    int k = idx >> 10, n = idx & 1023;
    bool hc = n < HH;
    int c = hc ? n : n - HH;
    g_W0x[idx] = hc ? Wh0[k * HH + c]        : Wo0[k * DD + c];
    g_W0r[idx] = hc ? Wh0[(DD + k) * HH + c] : Wo0[(DD + k) * DD + c];
    if (idx < 1024) g_b0[idx] = hc ? bh0[c] : bo0[c];
}

__global__ void init_state(const float* __restrict__ enc) {
    int idx = blockIdx.x * blockDim.x + threadIdx.x;
    if (idx < HH * BB) {
        int k = idx >> 6, b = idx & 63;
        g_h0T[0][k * 64 + b] = enc[b * HH + k];
        g_h1T[0][idx] = 0.0f;
    }
    if (idx == 0) g_bar = 0u;
}

// ---------------- GEMM 0: P0[m,0:1024] = x_row(m) @ W0x,  m = t*64+b -------
__global__ __launch_bounds__(256)
void gemm0(const float* __restrict__ x)
{
    __shared__ __align__(16) float2 As2[16][128];
    __shared__ __align__(16) float  Bs[16][128];

    const int tid = threadIdx.x;
    const int m0 = blockIdx.y * 128;
    const int n0 = blockIdx.x * 128;

    const int ai = tid >> 2;
    const int ak = (tid & 3) << 2;
    const int mg0 = m0 + ai, mg1 = m0 + ai + 64;
    const float* ap0 = x + (size_t)(mg0 & 63) * (TT * DD) + (size_t)(mg0 >> 6) * DD + ak;
    const float* ap1 = x + (size_t)(mg1 & 63) * (TT * DD) + (size_t)(mg1 >> 6) * DD + ak;

    const int bk = tid >> 5;
    const int bn = (tid & 31) << 2;
    const float* bp = g_W0x + (size_t)bk * 1024 + n0 + bn;

    const int ty = tid >> 4, tx = tid & 15;

    ull acc[8][4];
#pragma unroll
    for (int i = 0; i < 8; ++i)
#pragma unroll
        for (int j = 0; j < 4; ++j) acc[i][j] = 0ull;

    for (int k0 = 0; k0 < DD; k0 += 16) {
        float4 av0 = *(const float4*)(ap0 + k0);
        float4 av1 = *(const float4*)(ap1 + k0);
        float4 bv0 = *(const float4*)(bp + (size_t)k0 * 1024);
        float4 bv1 = *(const float4*)(bp + (size_t)(k0 + 8) * 1024);
        __syncthreads();
        As2[ak + 0][ai] = make_float2(av0.x, av0.x);
        As2[ak + 1][ai] = make_float2(av0.y, av0.y);
        As2[ak + 2][ai] = make_float2(av0.z, av0.z);
        As2[ak + 3][ai] = make_float2(av0.w, av0.w);
        As2[ak + 0][ai + 64] = make_float2(av1.x, av1.x);
        As2[ak + 1][ai + 64] = make_float2(av1.y, av1.y);
        As2[ak + 2][ai + 64] = make_float2(av1.z, av1.z);
        As2[ak + 3][ai + 64] = make_float2(av1.w, av1.w);
        *(float4*)&Bs[bk][bn]     = bv0;
        *(float4*)&Bs[bk + 8][bn] = bv1;
        __syncthreads();
#pragma unroll
        for (int k = 0; k < 16; ++k) {
            ulonglong2 a01 = *(const ulonglong2*)&As2[k][ty * 8 + 0];
            ulonglong2 a23 = *(const ulonglong2*)&As2[k][ty * 8 + 2];
            ulonglong2 a45 = *(const ulonglong2*)&As2[k][ty * 8 + 4];
            ulonglong2 a67 = *(const ulonglong2*)&As2[k][ty * 8 + 6];
            ulonglong2 b03 = *(const ulonglong2*)&Bs[k][tx * 8 + 0];
            ulonglong2 b47 = *(const ulonglong2*)&Bs[k][tx * 8 + 4];
            ull a[8] = {a01.x, a01.y, a23.x, a23.y, a45.x, a45.y, a67.x, a67.y};
            ull b[4] = {b03.x, b03.y, b47.x, b47.y};
#pragma unroll
            for (int i = 0; i < 8; ++i)
#pragma unroll
                for (int j = 0; j < 4; ++j)
                    acc[i][j] = ffma2(a[i], b[j], acc[i][j]);
        }
    }
#pragma unroll
    for (int i = 0; i < 8; ++i) {
        float* cp = g_P0 + (size_t)(m0 + ty * 8 + i) * 1024 + n0 + tx * 8;
        *(ulonglong2*)cp       = make_ulonglong2(acc[i][0], acc[i][1]);
        *(ulonglong2*)(cp + 4) = make_ulonglong2(acc[i][2], acc[i][3]);
    }
}

// ---------------- fused pipelined scan -------------------------------------
// bx < 64  : "A" CTA — 16 cols of [h0|o0], K=512 vs g_h0T
// bx >= 64 : "B" CTA — 8 cols of h1, K=1024 vs [o0_{t-1} | h1_{t-2}]
// Recurrent inputs staged L2->SMEM via cp.async double buffer (4 chunks/round).
// SMEM: Ws 32KB | stg0 64KB | stg1 64KB | red 16KB = 176 KB.
__global__ __launch_bounds__(256)
void scan_fused(const float* __restrict__ Wh1, const float* __restrict__ bh1)
{
    extern __shared__ __align__(16) float sm[];
    float* Ws   = sm;            // 8192 floats
    float* stg0 = sm + 8192;     // 16384 floats
    float* stg1 = sm + 24576;    // 16384 floats
    float* red  = sm + 40960;    // 4096 floats

    const int tid = threadIdx.x;
    const int bx  = blockIdx.x;
    const int w   = tid >> 5, ln = tid & 31;
    const int rr  = tid >> 2;
    const int jj  = (tid & 3) << 1;
    const ull* wsq = (const ull*)Ws;
    ull* redq = (ull*)red;

    const unsigned s0addr = (unsigned)__cvta_generic_to_shared(stg0);
    const unsigned s1addr = (unsigned)__cvta_generic_to_shared(stg1);

    if (bx < 64) {
        // ================= A: layer-0 recurrent part =================
        const int n0 = bx * 16;
        for (int i = tid; i < 512 * 16; i += 256) {
            int k = i >> 4, j = i & 15;
            Ws[i] = g_W0r[k * 1024 + n0 + j];
        }
        float bA00 = g_b0[n0 + jj],     bA01 = g_b0[n0 + jj + 1];
        float bA10 = g_b0[n0 + 8 + jj], bA11 = g_b0[n0 + 8 + jj + 1];
        __syncthreads();

        for (int r = 0; r < TT; ++r) {
            float2 p0 = ldcg2(&g_P0[((size_t)r * 64 + rr) * 1024 + n0 + jj]);
            float2 p1 = ldcg2(&g_P0[((size_t)r * 64 + rr) * 1024 + n0 + 8 + jj]);
            const float* hsrc = g_h0T[r & 1];

            // stage chunk 0 (128 k rows = 32 KB = 2048 float4, 8 per thread)
#pragma unroll
            for (int i = 0; i < 8; ++i)
                cpasync16(s0addr + (tid + i * 256) * 16, hsrc + (tid + i * 256) * 4);
            cp_commit();

            ull a0[8], a1[8];
#pragma unroll
            for (int q = 0; q < 8; ++q) { a0[q] = 0ull; a1[q] = 0ull; }

#pragma unroll
            for (int c = 0; c < 4; ++c) {
                if (c < 3) {
                    const unsigned dst = (c & 1) ? s0addr : s1addr;
                    const float* src = hsrc + (c + 1) * 8192;
#pragma unroll
                    for (int i = 0; i < 8; ++i)
                        cpasync16(dst + (tid + i * 256) * 16, src + (tid + i * 256) * 4);
                    cp_commit();
                    cp_wait<1>();
                } else {
                    cp_wait<0>();
                }
                __syncthreads();
                const float* hb = (c & 1) ? stg1 : stg0;
                const int kg = c * 128 + w * 16;
#pragma unroll 4
                for (int kk = 0; kk < 16; ++kk) {
                    float2 h2 = *(const float2*)(hb + (w * 16 + kk) * 64 + 2 * ln);
                    ull hx = dup2(h2.x), hy = dup2(h2.y);
                    const ulonglong2* wp = (const ulonglong2*)(wsq + (size_t)(kg + kk) * 8);
                    ulonglong2 u0 = wp[0], u1 = wp[1], u2 = wp[2], u3 = wp[3];
                    a0[0] = ffma2(hx, u0.x, a0[0]); a1[0] = ffma2(hy, u0.x, a1[0]);
                    a0[1] = ffma2(hx, u0.y, a0[1]); a1[1] = ffma2(hy, u0.y, a1[1]);
                    a0[2] = ffma2(hx, u1.x, a0[2]); a1[2] = ffma2(hy, u1.x, a1[2]);
                    a0[3] = ffma2(hx, u1.y, a0[3]); a1[3] = ffma2(hy, u1.y, a1[3]);
                    a0[4] = ffma2(hx, u2.x, a0[4]); a1[4] = ffma2(hy, u2.x, a1[4]);
                    a0[5] = ffma2(hx, u2.y, a0[5]); a1[5] = ffma2(hy, u2.y, a1[5]);
                    a0[6] = ffma2(hx, u3.x, a0[6]); a1[6] = ffma2(hy, u3.x, a1[6]);
                    a0[7] = ffma2(hx, u3.y, a0[7]); a1[7] = ffma2(hy, u3.y, a1[7]);
                }
                __syncthreads();
            }

            // two reduce passes of 8 cols each
#pragma unroll
            for (int p = 0; p < 2; ++p) {
#pragma unroll
                for (int q = 0; q < 4; ++q) {
                    redq[(w * 64 + 2 * ln)     * 4 + q] = a0[p * 4 + q];
                    redq[(w * 64 + 2 * ln + 1) * 4 + q] = a1[p * 4 + q];
                }
                __syncthreads();
                float s0 = (p ? p1.x : p0.x) + (p ? bA10 : bA00);
                float s1 = (p ? p1.y : p0.y) + (p ? bA11 : bA01);
#pragma unroll
                for (int ww = 0; ww < 8; ++ww) {
                    float2 t2 = *(const float2*)&red[(ww * 64 + rr) * 8 + jj];
                    s0 += t2.x; s1 += t2.y;
                }
                s0 = tanh_acc(s0);
                s1 = tanh_acc(s1);
                const int c = n0 + p * 8 + jj;
                if (n0 < 512) {
                    float* dst = g_h0T[(r + 1) & 1];
                    stcg(dst + (c)     * 64 + rr, s0);
                    stcg(dst + (c + 1) * 64 + rr, s1);
                } else {
                    float* dst = g_o0T[r];
                    stcg(dst + (c - 512) * 64 + rr, s0);
                    stcg(dst + (c - 511) * 64 + rr, s1);
                }
                __syncthreads();
            }
            if (r < TT - 1) {
                if (tid == 0) {
                    asm volatile("red.release.gpu.global.add.u32 [%0], 1;"
                                 :: "l"(&g_bar) : "memory");
                    const unsigned tgt = (unsigned)(r + 1) * 128u;
                    unsigned v;
                    do {
                        asm volatile("ld.acquire.gpu.global.u32 %0, [%1];"
                                     : "=r"(v) : "l"(&g_bar) : "memory");
                    } while (v < tgt);
                }
                __syncthreads();
            }
        }
    } else {
        // ================= B: layer-1 hidden chain (one step behind) =========
        const int c0 = (bx - 64) * 8;
        for (int i = tid; i < 1024 * 8; i += 256) {
            int k = i >> 3, j = i & 7;
            Ws[i] = Wh1[k * 512 + c0 + j];
        }
        const float b0v = bh1[c0 + jj], b1v = bh1[c0 + jj + 1];
        __syncthreads();

        for (int r = 0; r < TT; ++r) {
            if (r >= 1) {
                const int t1 = r - 1;
                const float* srcs[4] = {
                    g_o0T[t1],          g_o0T[t1] + 16384,
                    g_h1T[t1],          g_h1T[t1] + 16384
                };
                // stage chunk 0 (256 k rows = 64 KB = 4096 float4, 16 per thread)
#pragma unroll
                for (int i = 0; i < 16; ++i)
                    cpasync16(s0addr + (tid + i * 256) * 16, srcs[0] + (tid + i * 256) * 4);
                cp_commit();

                ull a0[4], a1[4];
#pragma unroll
                for (int q = 0; q < 4; ++q) { a0[q] = 0ull; a1[q] = 0ull; }

#pragma unroll
                for (int c = 0; c < 4; ++c) {
                    if (c < 3) {
                        const unsigned dst = (c & 1) ? s0addr : s1addr;
                        const float* src = srcs[c + 1];
#pragma unroll
                        for (int i = 0; i < 16; ++i)
                            cpasync16(dst + (tid + i * 256) * 16, src + (tid + i * 256) * 4);
                        cp_commit();
                        cp_wait<1>();
                    } else {
                        cp_wait<0>();
                    }
                    __syncthreads();
                    const float* hb = (c & 1) ? stg1 : stg0;
                    const int kg = c * 256 + w * 32;
#pragma unroll 4
                    for (int q = 0; q < 32; ++q) {
                        float2 h2 = *(const float2*)(hb + (w * 32 + q) * 64 + 2 * ln);
                        ull hx = dup2(h2.x), hy = dup2(h2.y);
                        const ulonglong2* wp = (const ulonglong2*)(wsq + (size_t)(kg + q) * 4);
                        ulonglong2 u0 = wp[0], u1 = wp[1];
                        a0[0] = ffma2(hx, u0.x, a0[0]); a1[0] = ffma2(hy, u0.x, a1[0]);
                        a0[1] = ffma2(hx, u0.y, a0[1]); a1[1] = ffma2(hy, u0.y, a1[1]);
                        a0[2] = ffma2(hx, u1.x, a0[2]); a1[2] = ffma2(hy, u1.x, a1[2]);
                        a0[3] = ffma2(hx, u1.y, a0[3]); a1[3] = ffma2(hy, u1.y, a1[3]);
                    }
                    __syncthreads();
                }
#pragma unroll
                for (int q = 0; q < 4; ++q) {
                    redq[(w * 64 + 2 * ln)     * 4 + q] = a0[q];
                    redq[(w * 64 + 2 * ln + 1) * 4 + q] = a1[q];
                }
                __syncthreads();
                float s0 = b0v, s1 = b1v;
#pragma unroll
                for (int ww = 0; ww < 8; ++ww) {
                    float2 t2 = *(const float2*)&red[(ww * 64 + rr) * 8 + jj];
                    s0 += t2.x; s1 += t2.y;
                }
                s0 = tanh_acc(s0);
                s1 = tanh_acc(s1);
                float* dst = g_h1T[r];
                stcg(dst + (c0 + jj)     * 64 + rr, s0);
                stcg(dst + (c0 + jj + 1) * 64 + rr, s1);
                __syncthreads();
            }
            if (r < TT - 1) {
                if (tid == 0) {
                    asm volatile("red.release.gpu.global.add.u32 [%0], 1;"
                                 :: "l"(&g_bar) : "memory");
                    const unsigned tgt = (unsigned)(r + 1) * 128u;
                    unsigned v;
                    do {
                        asm volatile("ld.acquire.gpu.global.u32 %0, [%1];"
                                     : "=r"(v) : "l"(&g_bar) : "memory");
                    } while (v < tgt);
                }
                __syncthreads();
            }
        }
    }
}

// ---------------- GEMM 1: out = tanh([o0_t | h1_{t-1}] @ Wo1 + bo1) --------
__global__ __launch_bounds__(256)
void gemm1(const float* __restrict__ Wo1, const float* __restrict__ bo1,
           float* __restrict__ out)
{
    __shared__ __align__(16) float2 As2[16][128];
    __shared__ __align__(16) float  Bs[16][128];

    const int tid = threadIdx.x;
    const int m0 = blockIdx.y * 128;
    const int n0 = blockIdx.x * 128;

    const int kk = tid >> 5;
    const int mm = (tid & 31) << 2;
    const int t  = (m0 >> 6) + (mm >> 6);
    const int b  = mm & 63;
    const size_t aoff = (size_t)t * (512 * 64) + b;

    const int bk = tid >> 5;
    const int bn = (tid & 31) << 2;

    const int ty = tid >> 4, tx = tid & 15;

    ull acc[8][4];
#pragma unroll
    for (int i = 0; i < 8; ++i)
#pragma unroll
        for (int j = 0; j < 4; ++j) acc[i][j] = 0ull;

    for (int k0 = 0; k0 < 1024; k0 += 16) {
        const float* Abase = (k0 < 512) ? &g_o0T[0][0] : &g_h1T[0][0];
        const int koff = (k0 < 512) ? k0 : (k0 - 512);
        float4 av0 = *(const float4*)(Abase + aoff + (size_t)(koff + kk) * 64);
        float4 av1 = *(const float4*)(Abase + aoff + (size_t)(koff + kk + 8) * 64);
        float4 bv0 = *(const float4*)(Wo1 + (size_t)(k0 + bk) * 512 + n0 + bn);
        float4 bv1 = *(const float4*)(Wo1 + (size_t)(k0 + bk + 8) * 512 + n0 + bn);
        __syncthreads();
        As2[kk][mm + 0] = make_float2(av0.x, av0.x);
        As2[kk][mm + 1] = make_float2(av0.y, av0.y);
        As2[kk][mm + 2] = make_float2(av0.z, av0.z);
        As2[kk][mm + 3] = make_float2(av0.w, av0.w);
        As2[kk + 8][mm + 0] = make_float2(av1.x, av1.x);
        As2[kk + 8][mm + 1] = make_float2(av1.y, av1.y);
        As2[kk + 8][mm + 2] = make_float2(av1.z, av1.z);
        As2[kk + 8][mm + 3] = make_float2(av1.w, av1.w);
        *(float4*)&Bs[bk][bn]     = bv0;
        *(float4*)&Bs[bk + 8][bn] = bv1;
        __syncthreads();
#pragma unroll
        for (int k = 0; k < 16; ++k) {
            ulonglong2 a01 = *(const ulonglong2*)&As2[k][ty * 8 + 0];
            ulonglong2 a23 = *(const ulonglong2*)&As2[k][ty * 8 + 2];
            ulonglong2 a45 = *(const ulonglong2*)&As2[k][ty * 8 + 4];
            ulonglong2 a67 = *(const ulonglong2*)&As2[k][ty * 8 + 6];
            ulonglong2 b03 = *(const ulonglong2*)&Bs[k][tx * 8 + 0];
            ulonglong2 b47 = *(const ulonglong2*)&Bs[k][tx * 8 + 4];
            ull a[8] = {a01.x, a01.y, a23.x, a23.y, a45.x, a45.y, a67.x, a67.y};
            ull b2[4] = {b03.x, b03.y, b47.x, b47.y};
#pragma unroll
            for (int i = 0; i < 8; ++i)
#pragma unroll
                for (int j = 0; j < 4; ++j)
                    acc[i][j] = ffma2(a[i], b2[j], acc[i][j]);
        }
    }

    float4 bia0 = *(const float4*)(bo1 + n0 + tx * 8);
    float4 bia1 = *(const float4*)(bo1 + n0 + tx * 8 + 4);
#pragma unroll
    for (int i = 0; i < 8; ++i) {
        const int m  = m0 + ty * 8 + i;
        const int tt = m >> 6, bb = m & 63;
        float* cp = out + ((size_t)bb * TT + tt) * 512 + n0 + tx * 8;
        float2 v0 = unpk(acc[i][0]);
        float2 v1 = unpk(acc[i][1]);
        float2 v2 = unpk(acc[i][2]);
        float2 v3 = unpk(acc[i][3]);
        float4 o0, o1;
        o0.x = tanh_acc(v0.x + bia0.x);
        o0.y = tanh_acc(v0.y + bia0.y);
        o0.z = tanh_acc(v1.x + bia0.z);
        o0.w = tanh_acc(v1.y + bia0.w);
        o1.x = tanh_acc(v2.x + bia1.x);
        o1.y = tanh_acc(v2.y + bia1.y);
        o1.z = tanh_acc(v3.x + bia1.z);
        o1.w = tanh_acc(v3.y + bia1.w);
        *(float4*)cp       = o0;
        *(float4*)(cp + 4) = o1;
    }
}

// ---------------- launch ---------------------------------------------------
extern "C" void kernel_launch(void* const* d_in, const int* in_sizes, int n_in,
                              void* d_out, int out_size)
{
    const float* x   = (const float*)d_in[0];
    const float* enc = (const float*)d_in[1];
    const float* Wh0 = (const float*)d_in[2];
    const float* bh0 = (const float*)d_in[3];
    const float* Wo0 = (const float*)d_in[4];
    const float* bo0 = (const float*)d_in[5];
    const float* Wh1 = (const float*)d_in[6];
    const float* bh1 = (const float*)d_in[7];
    const float* Wo1 = (const float*)d_in[8];
    const float* bo1 = (const float*)d_in[9];
    float* out = (float*)d_out;

    static int smem_set = 0;
    if (!smem_set) {
        cudaFuncSetAttribute(scan_fused,
                             cudaFuncAttributeMaxDynamicSharedMemorySize, 180224);
        smem_set = 1;
    }

    pack0<<<(DD * 1024 + 255) / 256, 256>>>(Wh0, Wo0, bh0, bo0);
    init_state<<<(HH * BB + 255) / 256, 256>>>(enc);
    gemm0<<<dim3(8, 128), 256>>>(x);
    scan_fused<<<128, 256, 180224>>>(Wh1, bh1);
    gemm1<<<dim3(4, 128), 256>>>(Wo1, bo1, out);
}